// round 9
// baseline (speedup 1.0000x reference)
#include <cuda_runtime.h>
#include <cuda_fp16.h>
#include <math.h>
#include <stdint.h>

#define Bb   8
#define Tn   2048
#define Dm   512
#define Sn   4
#define GH   64
#define Mtot (Bb*Tn)          // 16384
#define NROWS 1152            // 512 pred | 512 wenc | 64 gate | 64 zero-pad
#define KEXT  1024            // B: 512 hi | 512 lo
#define KA    512             // A: hi only

// ---------------- scratch (static device globals; zero-initialized) ----------------
__device__ __half g_Ahf[(size_t)Mtot*KA];          // [m][k] hi only
__device__ __half g_Bhf[(size_t)Sn*NROWS*KEXT];    // [s][n][k]; rows 1088.. stay zero
__device__ float g_wenc [(size_t)Sn*Mtot*Dm];
__device__ float g_hgate[(size_t)Sn*Mtot*GH];
__device__ float g_errsq[Mtot*Sn];
__device__ float g_err [Mtot*Sn];
__device__ float g_mu  [Tn*Sn];
__device__ float g_sig [Tn*Sn];
__device__ float g_seW [Sn*3*GH];                  // se . W1 per (s,state)
__device__ float g_g3  [(size_t)Mtot*Sn*3];
__device__ float g_g3m [Tn*Sn*3];
__device__ int   g_state[Tn*Sn];

// ---------------- prep: fp32 -> fp16 hi (A); zero errsq ----------------
__global__ void convA_kernel(const float* __restrict__ h)
{
    int i = blockIdx.x * blockDim.x + threadIdx.x;
    if (i < Mtot*Sn) g_errsq[i] = 0.f;
    if (i >= Mtot * Dm) return;
    g_Ahf[i] = __float2half(h[i]);
}

// transpose [d][n] -> [n][d] via 32x33 smem tile; hi/lo split for B
__global__ void convB_kernel(const float* __restrict__ pred_W, const float* __restrict__ write_W,
                             const float* __restrict__ gate_W1)
{
    __shared__ float tile[32][33];
    const int s = blockIdx.z;
    const int n0 = blockIdx.y * 32;      // 0..1087
    const int d0 = blockIdx.x * 32;      // 0..511
    const int tx = threadIdx.x, ty = threadIdx.y;   // 32 x 8

    const float* src; int strideN, ncol;
    if (n0 < 512)       { src = pred_W  + (size_t)s*512*512; strideN = 512; ncol = n0 + tx; }
    else if (n0 < 1024) { src = write_W + (size_t)s*512*512; strideN = 512; ncol = n0 - 512 + tx; }
    else                { src = gate_W1 + (size_t)s*521*64;  strideN = 64;  ncol = n0 - 1024 + tx; }

    #pragma unroll
    for (int i = 0; i < 4; i++)
        tile[ty + 8*i][tx] = src[(size_t)(d0 + ty + 8*i)*strideN + ncol];
    __syncthreads();
    #pragma unroll
    for (int i = 0; i < 4; i++) {
        float v = tile[tx][ty + 8*i];
        __half hi = __float2half(v);
        __half lo = __float2half(v - __half2float(hi));
        size_t base = ((size_t)s*NROWS + n0 + ty + 8*i)*KEXT + d0 + tx;
        g_Bhf[base]       = hi;
        g_Bhf[base + 512] = lo;
    }
}

// ================= mma.sync helpers =================
__device__ __forceinline__ uint32_t smem_u32(const void* p) {
    uint32_t a;
    asm("{ .reg .u64 t; cvta.to.shared.u64 t, %1; cvt.u32.u64 %0, t; }" : "=r"(a) : "l"(p));
    return a;
}
#define CP16(dst, src) asm volatile("cp.async.cg.shared.global [%0], [%1], 16;" :: "r"(dst), "l"(src))
#define CP_COMMIT()    asm volatile("cp.async.commit_group;" ::: "memory")
#define CP_WAIT1()     asm volatile("cp.async.wait_group 1;" ::: "memory")
#define LDSM4(r0,r1,r2,r3,addr) \
    asm volatile("ldmatrix.sync.aligned.m8n8.x4.shared.b16 {%0,%1,%2,%3}, [%4];" \
        : "=r"(r0),"=r"(r1),"=r"(r2),"=r"(r3) : "r"(addr))
#define MMA16816(d, a, b) \
    asm volatile("mma.sync.aligned.m16n8k16.row.col.f32.f16.f16.f32 " \
        "{%0,%1,%2,%3},{%4,%5,%6,%7},{%8,%9},{%0,%1,%2,%3};" \
        : "+f"((d)[0]),"+f"((d)[1]),"+f"((d)[2]),"+f"((d)[3]) \
        : "r"((a)[0]),"r"((a)[1]),"r"((a)[2]),"r"((a)[3]), "r"((b)[0]),"r"((b)[1]))

#define PITCH    72
#define ROWB     (PITCH*2)          // 144 bytes per row
#define ATILE_B  (128*ROWB)         // 18432 bytes
#define BTILE_B  (128*ROWB)
#define STAGES   3
#define GEMM_SMEM (STAGES*(ATILE_B + BTILE_B))   // 110592

// blockIdx.x: 0..3 preds (1-pass), 4..7 wenc (2-pass), 8 gate (1-pass)
__global__ void __launch_bounds__(256, 2)
gemm_mma(const float* __restrict__ pred_b, const float* __restrict__ write_b,
         const float* __restrict__ gate_b1, const float* __restrict__ hseq)
{
    extern __shared__ __align__(16) char smem[];
    const uint32_t sAu = smem_u32(smem);
    const uint32_t sBu = sAu + STAGES*ATILE_B;

    const int tid = threadIdx.x;
    const int wid = tid >> 5, lane = tid & 31;
    const int s = blockIdx.z;
    const int mbase = blockIdx.y * 128;

    int which, nbase, colbase, NT;
    {
        const int x = blockIdx.x;
        if (x < 4)      { which = 0; nbase = x*128;           colbase = x*128;       NT = 8;  }
        else if (x < 8) { which = 1; nbase = 512 + (x-4)*128; colbase = (x-4)*128;   NT = 16; }
        else            { which = 2; nbase = 1024;            colbase = 0;           NT = 8;  }
    }

    const int mw = wid >> 2, nw = wid & 3;
    const int m0 = mw * 64;
    const int n0 = nw * 32;

    const int idx = lane & 7, sel = lane >> 3;
    const uint32_t aAddrBase = sAu + (uint32_t)(m0 + (sel&1)*8 + idx) * ROWB + (uint32_t)((sel>>1)*8)*2;
    const uint32_t bAddrBase = sBu + (uint32_t)(n0 + (sel>>1)*8 + idx) * ROWB + (uint32_t)((sel&1)*8)*2;

    float acc[4][4][4];
    #pragma unroll
    for (int i = 0; i < 4; i++)
        #pragma unroll
        for (int j = 0; j < 4; j++)
            #pragma unroll
            for (int q = 0; q < 4; q++) acc[i][j][q] = 0.f;

    const char* Aall = (const char*)g_Ahf;
    const char* Ball = (const char*)g_Bhf;

    // chunk c: A col = (c&7)*64 (hi only); B col = (c>>3)*512 + (c&7)*64 (hi then lo)
    auto load_tile = [&](int c, int slot) {
        const int acol = (c & 7) * 64;
        const int bcol = ((c >> 3) ? 512 : 0) + (c & 7) * 64;
        const uint32_t ab = sAu + slot * ATILE_B;
        const uint32_t bb = sBu + slot * BTILE_B;
        #pragma unroll
        for (int it = 0; it < 4; it++) {
            int g = tid + it*256;                 // 1024 granules: row*8 + gc
            int row = g >> 3, gc = g & 7;
            CP16(ab + row*ROWB + gc*16,
                 Aall + ((size_t)(mbase + row)*KA + acol + gc*8)*2);
        }
        #pragma unroll
        for (int it = 0; it < 4; it++) {
            int g = tid + it*256;
            int row = g >> 3, gc = g & 7;
            CP16(bb + row*ROWB + gc*16,
                 Ball + (((size_t)s*NROWS + nbase + row)*KEXT + bcol + gc*8)*2);
        }
        CP_COMMIT();
    };

    load_tile(0, 0);
    load_tile(1, 1);
    int slot = 0;
    for (int c = 0; c < NT; c++) {
        CP_WAIT1();
        __syncthreads();
        if (c + 2 < NT) load_tile(c + 2, (c + 2) % STAGES);
        else CP_COMMIT();
        const uint32_t aOff = aAddrBase + slot*ATILE_B;
        const uint32_t bOff = bAddrBase + slot*BTILE_B;
        #pragma unroll
        for (int ks = 0; ks < 4; ks++) {
            uint32_t afr[4][4], bfr[4][2];
            #pragma unroll
            for (int i = 0; i < 4; i++)
                LDSM4(afr[i][0], afr[i][1], afr[i][2], afr[i][3],
                      aOff + i*16*ROWB + ks*32);
            #pragma unroll
            for (int jp = 0; jp < 2; jp++) {
                uint32_t r0, r1, r2, r3;
                LDSM4(r0, r1, r2, r3, bOff + jp*16*ROWB + ks*32);
                bfr[jp*2+0][0] = r0; bfr[jp*2+0][1] = r1;
                bfr[jp*2+1][0] = r2; bfr[jp*2+1][1] = r3;
            }
            #pragma unroll
            for (int i = 0; i < 4; i++)
                #pragma unroll
                for (int j = 0; j < 4; j++)
                    MMA16816(acc[i][j], afr[i], bfr[j]);
        }
        slot = (slot + 1 == STAGES) ? 0 : slot + 1;
    }

    // ---------------- epilogue ----------------
    const int rbase = mbase + m0 + (lane >> 2);
    const int cbase = colbase + n0 + (lane & 3) * 2;

    if (which == 0) {
        // fused err: sum (pred - h[r+1])^2, atomic into g_errsq
        const float* bias = pred_b + s*Dm;
        float rowsum[4][2];
        #pragma unroll
        for (int i = 0; i < 4; i++) { rowsum[i][0] = 0.f; rowsum[i][1] = 0.f; }
        #pragma unroll
        for (int j = 0; j < 4; j++) {
            const int col = cbase + j*8;
            const float b0 = __ldg(bias + col), b1 = __ldg(bias + col + 1);
            #pragma unroll
            for (int i = 0; i < 4; i++) {
                const int r1 = rbase + i*16, r2 = r1 + 8;
                float2 h1 = *(const float2*)(hseq + (size_t)(r1+1)*Dm + col);
                float2 h2 = *(const float2*)(hseq + (size_t)(r2+1)*Dm + col);
                float d0 = acc[i][j][0] + b0 - h1.x;
                float d1 = acc[i][j][1] + b1 - h1.y;
                float d2 = acc[i][j][2] + b0 - h2.x;
                float d3 = acc[i][j][3] + b1 - h2.y;
                rowsum[i][0] += d0*d0 + d1*d1;
                rowsum[i][1] += d2*d2 + d3*d3;
            }
        }
        #pragma unroll
        for (int i = 0; i < 4; i++) {
            #pragma unroll
            for (int hh = 0; hh < 2; hh++) {
                float v = rowsum[i][hh];
                v += __shfl_xor_sync(0xffffffffu, v, 1);
                v += __shfl_xor_sync(0xffffffffu, v, 2);
                if ((lane & 3) == 0) {
                    int r = rbase + i*16 + hh*8;
                    if ((r & (Tn - 1)) != Tn - 1)
                        atomicAdd(&g_errsq[(r + 1)*Sn + s], v);
                }
            }
        }
        return;
    }

    if (which == 2 && n0 >= GH) return;   // gate tile: only cols 0..63 valid

    float* Cm; const float* bias; int stride;
    if (which == 1) { Cm = g_wenc + (size_t)s*Mtot*Dm; bias = write_b + s*Dm; stride = Dm; }
    else            { Cm = g_hgate + (size_t)s*Mtot*GH; bias = gate_b1 + s*GH; stride = GH; }

    #pragma unroll
    for (int j = 0; j < 4; j++) {
        const int col = cbase + j*8;
        const float b0 = __ldg(bias + col), b1 = __ldg(bias + col + 1);
        #pragma unroll
        for (int i = 0; i < 4; i++) {
            const int r = rbase + i*16;
            float2 o0 = { acc[i][j][0] + b0, acc[i][j][1] + b1 };
            float2 o1 = { acc[i][j][2] + b0, acc[i][j][3] + b1 };
            *(float2*)(Cm + (size_t)r*stride + col)       = o0;
            *(float2*)(Cm + (size_t)(r+8)*stride + col)   = o1;
        }
    }
}

// ---------------- fused stats: err, mean, mu-scan, mad, sigma-scan, seW ----------------
__global__ void stats_kernel(const float* __restrict__ gate_W1, const float* __restrict__ se)
{
    __shared__ float buf[Tn*Sn];      // 32KB
    const int tid = threadIdx.x;      // 1024 threads

    // A: err = sqrt(errsq + 1e-8), 0 at t=0; also zero g_g3m
    for (int i = tid; i < Mtot*Sn; i += 1024) {
        int t = (i >> 2) & (Tn - 1);
        g_err[i] = (t == 0) ? 0.f : sqrtf(g_errsq[i] + 1e-8f);
    }
    for (int i = tid; i < Tn*Sn*3; i += 1024) g_g3m[i] = 0.f;
    __syncthreads();

    // B: batch mean of err -> buf
    for (int i = tid; i < Tn*Sn; i += 1024) {
        int s = i & 3, t = i >> 2;
        float acc = 0.f;
        #pragma unroll
        for (int b = 0; b < Bb; b++) acc += g_err[((b*Tn + t))*Sn + s];
        buf[i] = acc * 0.125f;
    }
    __syncthreads();

    // C: mu scan; store carry to g_mu and overwrite buf with carry (for mad)
    if (tid < Sn) {
        int s = tid;
        float mu = 0.f;
        for (int t = 0; t < Tn; t++) {
            float av = buf[t*Sn + s];
            g_mu[t*Sn + s] = mu;
            buf[t*Sn + s] = mu;
            if (t > 0) mu = 0.99f*mu + 0.01f*av;
        }
    }
    __syncthreads();

    // D: mad means using buf (mu carry); overwrite buf with mad
    for (int i = tid; i < Tn*Sn; i += 1024) {
        int s = i & 3, t = i >> 2;
        float mu = buf[i];
        float acc = 0.f;
        #pragma unroll
        for (int b = 0; b < Bb; b++) acc += fabsf(g_err[((b*Tn + t))*Sn + s] - mu);
        buf[i] = acc * 0.125f;
    }
    __syncthreads();

    // E: sigma scan
    if (tid < Sn) {
        int s = tid;
        float sg = 1.f;
        for (int t = 0; t < Tn; t++) {
            float mv = buf[t*Sn + s];
            g_sig[t*Sn + s] = sg;
            if (t > 0) sg = 0.99f*sg + 0.01f*mv;
        }
    }

    // F: seW[s][st][h] = sum_e se[st][e] * W1[s][513+e][h]
    for (int i = tid; i < Sn*3*GH; i += 1024) {
        int hcol = i & 63;
        int r = i >> 6;
        int st = r % 3, s = r / 3;
        float acc = 0.f;
        #pragma unroll
        for (int e = 0; e < 8; e++)
            acc += se[st*8 + e] * gate_W1[(size_t)s*521*GH + (513+e)*GH + hcol];
        g_seW[i] = acc;
    }
}

// ---------------- gate for all 3 hypothetical states (z inline, seW table) ----------------
__global__ void gate3_kernel(const float* __restrict__ gate_W1, const float* __restrict__ gate_W2,
                             const float* __restrict__ gate_b2)
{
    int gw = (blockIdx.x * blockDim.x + threadIdx.x) >> 5;
    int lane = threadIdx.x & 31;
    if (gw >= Mtot * Sn) return;
    int s = gw & 3, m = gw >> 2;
    int t = m & (Tn - 1);
    const float* W1z = gate_W1 + (size_t)s * 521 * GH + 512*GH;
    const float* hb = g_hgate + ((size_t)s*Mtot + m) * GH;

    float zz = (t == 0) ? 0.f
             : (g_err[m*Sn + s] - g_mu[t*Sn + s]) / fmaxf(g_sig[t*Sn + s], 1e-3f);
    float base0 = hb[lane]      + zz * __ldg(W1z + lane);
    float base1 = hb[lane + 32] + zz * __ldg(W1z + lane + 32);
    float w20 = __ldg(gate_W2 + s*GH + lane), w21 = __ldg(gate_W2 + s*GH + lane + 32);
    float b2 = __ldg(gate_b2 + s);
    #pragma unroll
    for (int st = 0; st < 3; st++) {
        float s0 = __ldg(g_seW + (s*3 + st)*GH + lane);
        float s1 = __ldg(g_seW + (s*3 + st)*GH + lane + 32);
        float v = fmaxf(base0 + s0, 0.f)*w20 + fmaxf(base1 + s1, 0.f)*w21;
        #pragma unroll
        for (int o = 16; o; o >>= 1) v += __shfl_down_sync(0xffffffffu, v, o);
        if (!lane) g_g3[((size_t)m*Sn + s)*3 + st] = 1.f / (1.f + expf(-(v + b2)));
    }
}

// deterministic batch mean of g3 (sequential over b; no atomics near state thresholds)
__global__ void g3mean_kernel()
{
    int i = blockIdx.x * blockDim.x + threadIdx.x;
    if (i >= Tn*Sn*3) return;
    int st = i % 3, r = i / 3;
    int s = r & 3, t = r >> 2;
    float acc = 0.f;
    #pragma unroll
    for (int b = 0; b < Bb; b++)
        acc += g_g3[(((size_t)b*Tn + t)*Sn + s)*3 + st];
    g_g3m[i] = acc * 0.125f;
}

__global__ void state_scan_kernel()
{
    __shared__ float sm[12288];
    float ema = 0.5f; int cur = 0;
    for (int ph = 0; ph < 2; ph++) {
        __syncthreads();
        for (int i = threadIdx.x; i < 12288; i += blockDim.x) sm[i] = g_g3m[ph*12288 + i];
        __syncthreads();
        if (threadIdx.x < Sn) {
            int s = threadIdx.x;
            for (int tt = 0; tt < 1024; tt++) {
                int t = ph*1024 + tt;
                g_state[t*Sn + s] = cur;
                float gm = sm[(tt*Sn + s)*3 + cur];
                ema = 0.99f*ema + 0.01f*gm;
                if (cur == 0)      { if (ema < 0.1f)  cur = 1; }
                else if (cur == 1) { if (ema < 0.03f) cur = 2; else if (ema > 0.25f) cur = 0; }
                else               { if (ema > 0.25f) cur = 0; }
            }
        }
    }
}

// ---------------- m recurrence: geff inline; 256 CTAs x 64 threads ----------------
__global__ void mscan_kernel(const float* __restrict__ w0, float* __restrict__ out)
{
    int blk = blockIdx.x;              // 256 blocks
    int dc = blk & 7;
    int bs = blk >> 3;
    int s = bs & 3, b = bs >> 2;
    int d = dc*64 + threadIdx.x;

    const float* wp = g_wenc + ((size_t)s*Mtot + (size_t)b*Tn)*Dm + d;
    float* op = out + (size_t)b*Tn*(Sn*Dm) + s*Dm + d;
    const size_t g3base = ((size_t)b*Tn)*Sn + s;

    float m = w0[s*Dm + d];
    for (int t0 = 0; t0 < Tn; t0 += 16) {
        float ge[16], w[16];
        #pragma unroll
        for (int u = 0; u < 16; u++) {
            int t = t0 + u;
            int st = __ldg(g_state + t*Sn + s);
            float gm = __ldg(g_g3 + (g3base + (size_t)t*Sn)*3 + st);
            float gn = (st == 0) ? 1.0f : ((st == 1) ? 0.5f : 0.1f);
            ge[u] = gm * gn;
            w[u]  = __ldg(wp + (size_t)t*Dm);
        }
        #pragma unroll
        for (int u = 0; u < 16; u++) {
            m = (1.f - ge[u])*m + ge[u]*w[u];
            op[(size_t)(t0+u)*(Sn*Dm)] = m;
        }
    }
}

// ---------------- launch ----------------
extern "C" void kernel_launch(void* const* d_in, const int* in_sizes, int n_in,
                              void* d_out, int out_size)
{
    const float* h        = (const float*)d_in[0];
    const float* pred_W   = (const float*)d_in[1];
    const float* pred_b   = (const float*)d_in[2];
    const float* gate_W1  = (const float*)d_in[3];
    const float* gate_b1  = (const float*)d_in[4];
    const float* gate_W2  = (const float*)d_in[5];
    const float* gate_b2  = (const float*)d_in[6];
    const float* write_W  = (const float*)d_in[7];
    const float* write_b  = (const float*)d_in[8];
    const float* w0       = (const float*)d_in[9];
    const float* st_embed = (const float*)d_in[10];
    float* out = (float*)d_out;

    static bool attr_done = false;
    if (!attr_done) {
        cudaFuncSetAttribute(gemm_mma, cudaFuncAttributeMaxDynamicSharedMemorySize, GEMM_SMEM);
        attr_done = true;
    }

    convA_kernel<<<(Mtot*Dm + 255)/256, 256>>>(h);
    convB_kernel<<<dim3(16, 34, Sn), dim3(32, 8)>>>(pred_W, write_W, gate_W1);

    gemm_mma<<<dim3(9, 128, Sn), 256, GEMM_SMEM>>>(pred_b, write_b, gate_b1, h);

    stats_kernel<<<1, 1024>>>(gate_W1, st_embed);
    gate3_kernel<<<(Mtot*Sn*32 + 255)/256, 256>>>(gate_W1, gate_W2, gate_b2);
    g3mean_kernel<<<(Tn*Sn*3 + 255)/256, 256>>>();
    state_scan_kernel<<<1, 256>>>();
    mscan_kernel<<<256, 64>>>(w0, out);
}

// round 10
// speedup vs baseline: 1.2705x; 1.2705x over previous
#include <cuda_runtime.h>
#include <cuda_fp16.h>
#include <math.h>
#include <stdint.h>

#define Bb   8
#define Tn   2048
#define Dm   512
#define Sn   4
#define GH   64
#define Mtot (Bb*Tn)          // 16384
#define NROWS 1152            // 512 pred | 512 wenc | 64 gate | 64 zero-pad
#define KEXT  1024            // B: 512 hi | 512 lo
#define KA    512             // A: hi only

// ---------------- scratch (static device globals; zero-initialized) ----------------
__device__ __half g_Ahf[(size_t)Mtot*KA];          // [m][k] hi only
__device__ __half g_Bhf[(size_t)Sn*NROWS*KEXT];    // [s][n][k]; rows 1088.. stay zero
__device__ float g_wenc [(size_t)Sn*Mtot*Dm];
__device__ float g_hgate[(size_t)Sn*Mtot*GH];
__device__ float g_errsq[Mtot*Sn];
__device__ float g_err [Mtot*Sn];
__device__ float g_z   [Mtot*Sn];
__device__ float g_a   [Tn*Sn];
__device__ float g_mu  [Tn*Sn];
__device__ float g_mad [Tn*Sn];
__device__ float g_sig [Tn*Sn];
__device__ float g_g3  [(size_t)Mtot*Sn*3];
__device__ float g_g3m [Tn*Sn*3];
__device__ int   g_state[Tn*Sn];
__device__ float g_geff[Mtot*Sn];

// ---------------- prep: fp32 -> fp16 hi (A); also zero errsq ----------------
__global__ void convA_kernel(const float* __restrict__ h)
{
    int i = blockIdx.x * blockDim.x + threadIdx.x;
    if (i < Mtot*Sn) g_errsq[i] = 0.f;
    if (i >= Mtot * Dm) return;
    g_Ahf[i] = __float2half(h[i]);
}

// transpose [d][n] -> [n][d] via 32x33 smem tile; hi/lo split for B
__global__ void convB_kernel(const float* __restrict__ pred_W, const float* __restrict__ write_W,
                             const float* __restrict__ gate_W1)
{
    __shared__ float tile[32][33];
    const int s = blockIdx.z;
    const int n0 = blockIdx.y * 32;      // 0..1087
    const int d0 = blockIdx.x * 32;      // 0..511
    const int tx = threadIdx.x, ty = threadIdx.y;   // 32 x 8

    const float* src; int strideN, ncol;
    if (n0 < 512)       { src = pred_W  + (size_t)s*512*512; strideN = 512; ncol = n0 + tx; }
    else if (n0 < 1024) { src = write_W + (size_t)s*512*512; strideN = 512; ncol = n0 - 512 + tx; }
    else                { src = gate_W1 + (size_t)s*521*64;  strideN = 64;  ncol = n0 - 1024 + tx; }

    #pragma unroll
    for (int i = 0; i < 4; i++)
        tile[ty + 8*i][tx] = src[(size_t)(d0 + ty + 8*i)*strideN + ncol];
    __syncthreads();
    #pragma unroll
    for (int i = 0; i < 4; i++) {
        float v = tile[tx][ty + 8*i];
        __half hi = __float2half(v);
        __half lo = __float2half(v - __half2float(hi));
        size_t base = ((size_t)s*NROWS + n0 + ty + 8*i)*KEXT + d0 + tx;
        g_Bhf[base]       = hi;
        g_Bhf[base + 512] = lo;
    }
}

// ================= mma.sync helpers =================
__device__ __forceinline__ uint32_t smem_u32(const void* p) {
    uint32_t a;
    asm("{ .reg .u64 t; cvta.to.shared.u64 t, %1; cvt.u32.u64 %0, t; }" : "=r"(a) : "l"(p));
    return a;
}
#define CP16(dst, src) asm volatile("cp.async.cg.shared.global [%0], [%1], 16;" :: "r"(dst), "l"(src))
#define CP_COMMIT()    asm volatile("cp.async.commit_group;" ::: "memory")
#define CP_WAIT1()     asm volatile("cp.async.wait_group 1;" ::: "memory")
#define LDSM4(r0,r1,r2,r3,addr) \
    asm volatile("ldmatrix.sync.aligned.m8n8.x4.shared.b16 {%0,%1,%2,%3}, [%4];" \
        : "=r"(r0),"=r"(r1),"=r"(r2),"=r"(r3) : "r"(addr))
#define MMA16816(d, a, b) \
    asm volatile("mma.sync.aligned.m16n8k16.row.col.f32.f16.f16.f32 " \
        "{%0,%1,%2,%3},{%4,%5,%6,%7},{%8,%9},{%0,%1,%2,%3};" \
        : "+f"((d)[0]),"+f"((d)[1]),"+f"((d)[2]),"+f"((d)[3]) \
        : "r"((a)[0]),"r"((a)[1]),"r"((a)[2]),"r"((a)[3]), "r"((b)[0]),"r"((b)[1]))

#define PITCH    72
#define ROWB     (PITCH*2)          // 144 bytes per row
#define ATILE_B  (128*ROWB)         // 18432 bytes
#define BTILE_B  (128*ROWB)
#define STAGES   3
#define GEMM_SMEM (STAGES*(ATILE_B + BTILE_B))   // 110592

// blockIdx.x: 0..3 preds (1-pass), 4..7 wenc (2-pass), 8 gate (1-pass)
__global__ void __launch_bounds__(256, 2)
gemm_mma(const float* __restrict__ pred_b, const float* __restrict__ write_b,
         const float* __restrict__ gate_b1, const float* __restrict__ hseq)
{
    extern __shared__ __align__(16) char smem[];
    const uint32_t sAu = smem_u32(smem);
    const uint32_t sBu = sAu + STAGES*ATILE_B;

    const int tid = threadIdx.x;
    const int wid = tid >> 5, lane = tid & 31;
    const int s = blockIdx.z;
    const int mbase = blockIdx.y * 128;

    int which, nbase, colbase, NT;
    {
        const int x = blockIdx.x;
        if (x < 4)      { which = 0; nbase = x*128;           colbase = x*128;       NT = 8;  }
        else if (x < 8) { which = 1; nbase = 512 + (x-4)*128; colbase = (x-4)*128;   NT = 16; }
        else            { which = 2; nbase = 1024;            colbase = 0;           NT = 8;  }
    }

    const int mw = wid >> 2, nw = wid & 3;
    const int m0 = mw * 64;
    const int n0 = nw * 32;

    const int idx = lane & 7, sel = lane >> 3;
    const uint32_t aAddrBase = sAu + (uint32_t)(m0 + (sel&1)*8 + idx) * ROWB + (uint32_t)((sel>>1)*8)*2;
    const uint32_t bAddrBase = sBu + (uint32_t)(n0 + (sel>>1)*8 + idx) * ROWB + (uint32_t)((sel&1)*8)*2;

    float acc[4][4][4];
    #pragma unroll
    for (int i = 0; i < 4; i++)
        #pragma unroll
        for (int j = 0; j < 4; j++)
            #pragma unroll
            for (int q = 0; q < 4; q++) acc[i][j][q] = 0.f;

    const char* Aall = (const char*)g_Ahf;
    const char* Ball = (const char*)g_Bhf;

    // chunk c: A col = (c&7)*64 (hi only); B col = (c>>3)*512 + (c&7)*64 (hi then lo)
    auto load_tile = [&](int c, int slot) {
        const int acol = (c & 7) * 64;
        const int bcol = ((c >> 3) ? 512 : 0) + (c & 7) * 64;
        const uint32_t ab = sAu + slot * ATILE_B;
        const uint32_t bb = sBu + slot * BTILE_B;
        #pragma unroll
        for (int it = 0; it < 4; it++) {
            int g = tid + it*256;                 // 1024 granules: row*8 + gc
            int row = g >> 3, gc = g & 7;
            CP16(ab + row*ROWB + gc*16,
                 Aall + ((size_t)(mbase + row)*KA + acol + gc*8)*2);
        }
        #pragma unroll
        for (int it = 0; it < 4; it++) {
            int g = tid + it*256;
            int row = g >> 3, gc = g & 7;
            CP16(bb + row*ROWB + gc*16,
                 Ball + (((size_t)s*NROWS + nbase + row)*KEXT + bcol + gc*8)*2);
        }
        CP_COMMIT();
    };

    load_tile(0, 0);
    load_tile(1, 1);
    int slot = 0;
    for (int c = 0; c < NT; c++) {
        CP_WAIT1();
        __syncthreads();
        if (c + 2 < NT) load_tile(c + 2, (c + 2) % STAGES);
        else CP_COMMIT();
        const uint32_t aOff = aAddrBase + slot*ATILE_B;
        const uint32_t bOff = bAddrBase + slot*BTILE_B;
        #pragma unroll
        for (int ks = 0; ks < 4; ks++) {
            uint32_t afr[4][4], bfr[4][2];
            #pragma unroll
            for (int i = 0; i < 4; i++)
                LDSM4(afr[i][0], afr[i][1], afr[i][2], afr[i][3],
                      aOff + i*16*ROWB + ks*32);
            #pragma unroll
            for (int jp = 0; jp < 2; jp++) {
                uint32_t r0, r1, r2, r3;
                LDSM4(r0, r1, r2, r3, bOff + jp*16*ROWB + ks*32);
                bfr[jp*2+0][0] = r0; bfr[jp*2+0][1] = r1;
                bfr[jp*2+1][0] = r2; bfr[jp*2+1][1] = r3;
            }
            #pragma unroll
            for (int i = 0; i < 4; i++)
                #pragma unroll
                for (int j = 0; j < 4; j++)
                    MMA16816(acc[i][j], afr[i], bfr[j]);
        }
        slot = (slot + 1 == STAGES) ? 0 : slot + 1;
    }

    // ---------------- epilogue ----------------
    const int rbase = mbase + m0 + (lane >> 2);
    const int cbase = colbase + n0 + (lane & 3) * 2;

    if (which == 0) {
        // fused err: sum (pred - h[r+1])^2, atomic into g_errsq
        const float* bias = pred_b + s*Dm;
        float rowsum[4][2];
        #pragma unroll
        for (int i = 0; i < 4; i++) { rowsum[i][0] = 0.f; rowsum[i][1] = 0.f; }
        #pragma unroll
        for (int j = 0; j < 4; j++) {
            const int col = cbase + j*8;
            const float b0 = __ldg(bias + col), b1 = __ldg(bias + col + 1);
            #pragma unroll
            for (int i = 0; i < 4; i++) {
                const int r1 = rbase + i*16, r2 = r1 + 8;
                float2 h1 = *(const float2*)(hseq + (size_t)(r1+1)*Dm + col);
                float2 h2 = *(const float2*)(hseq + (size_t)(r2+1)*Dm + col);
                float d0 = acc[i][j][0] + b0 - h1.x;
                float d1 = acc[i][j][1] + b1 - h1.y;
                float d2 = acc[i][j][2] + b0 - h2.x;
                float d3 = acc[i][j][3] + b1 - h2.y;
                rowsum[i][0] += d0*d0 + d1*d1;
                rowsum[i][1] += d2*d2 + d3*d3;
            }
        }
        #pragma unroll
        for (int i = 0; i < 4; i++) {
            #pragma unroll
            for (int hh = 0; hh < 2; hh++) {
                float v = rowsum[i][hh];
                v += __shfl_xor_sync(0xffffffffu, v, 1);
                v += __shfl_xor_sync(0xffffffffu, v, 2);
                if ((lane & 3) == 0) {
                    int r = rbase + i*16 + hh*8;
                    if ((r & (Tn - 1)) != Tn - 1)
                        atomicAdd(&g_errsq[(r + 1)*Sn + s], v);
                }
            }
        }
        return;
    }

    if (which == 2 && n0 >= GH) return;   // gate tile: only cols 0..63 valid

    float* Cm; const float* bias; int stride;
    if (which == 1) { Cm = g_wenc + (size_t)s*Mtot*Dm; bias = write_b + s*Dm; stride = Dm; }
    else            { Cm = g_hgate + (size_t)s*Mtot*GH; bias = gate_b1 + s*GH; stride = GH; }

    #pragma unroll
    for (int j = 0; j < 4; j++) {
        const int col = cbase + j*8;
        const float b0 = __ldg(bias + col), b1 = __ldg(bias + col + 1);
        #pragma unroll
        for (int i = 0; i < 4; i++) {
            const int r = rbase + i*16;
            float2 o0 = { acc[i][j][0] + b0, acc[i][j][1] + b1 };
            float2 o1 = { acc[i][j][2] + b0, acc[i][j][3] + b1 };
            *(float2*)(Cm + (size_t)r*stride + col)       = o0;
            *(float2*)(Cm + (size_t)(r+8)*stride + col)   = o1;
        }
    }
}

// ---------------- err finalize: sqrt(sum + 1e-8), 0 at t=0 ----------------
__global__ void err_finalize_kernel()
{
    int i = blockIdx.x * blockDim.x + threadIdx.x;
    if (i >= Mtot * Sn) return;
    int t = (i >> 2) & (Tn - 1);
    g_err[i] = (t == 0) ? 0.f : sqrtf(g_errsq[i] + 1e-8f);
}

__global__ void errmean_kernel()
{
    int i = blockIdx.x * blockDim.x + threadIdx.x;
    if (i >= Tn * Sn) return;
    int s = i & 3, t = i >> 2;
    float acc = 0.f;
    #pragma unroll
    for (int b = 0; b < Bb; b++) acc += g_err[((size_t)(b*Tn + t))*Sn + s];
    g_a[i] = acc * 0.125f;
}

__global__ void scan_mu_kernel()
{
    __shared__ float sm[Tn*Sn];
    for (int i = threadIdx.x; i < Tn*Sn; i += blockDim.x) sm[i] = g_a[i];
    __syncthreads();
    if (threadIdx.x < Sn) {
        int s = threadIdx.x;
        float mu = 0.f;
        for (int t = 0; t < Tn; t++) {
            g_mu[t*Sn + s] = mu;
            if (t > 0) mu = 0.99f*mu + 0.01f*sm[t*Sn + s];
        }
    }
}

__global__ void mad_kernel()
{
    int i = blockIdx.x * blockDim.x + threadIdx.x;
    if (i >= Tn * Sn) return;
    int s = i & 3, t = i >> 2;
    float mu = g_mu[i];
    float acc = 0.f;
    #pragma unroll
    for (int b = 0; b < Bb; b++) acc += fabsf(g_err[((size_t)(b*Tn + t))*Sn + s] - mu);
    g_mad[i] = acc * 0.125f;
}

__global__ void scan_sigma_kernel()
{
    __shared__ float sm[Tn*Sn];
    for (int i = threadIdx.x; i < Tn*Sn; i += blockDim.x) sm[i] = g_mad[i];
    __syncthreads();
    if (threadIdx.x < Sn) {
        int s = threadIdx.x;
        float sg = 1.f;
        for (int t = 0; t < Tn; t++) {
            g_sig[t*Sn + s] = sg;
            if (t > 0) sg = 0.99f*sg + 0.01f*sm[t*Sn + s];
        }
    }
}

__global__ void z_kernel()
{
    int i = blockIdx.x * blockDim.x + threadIdx.x;
    if (i >= Mtot * Sn) return;
    int s = i & 3, m = i >> 2;
    int t = m & (Tn - 1);
    g_z[i] = (t == 0) ? 0.f
                      : (g_err[i] - g_mu[t*Sn + s]) / fmaxf(g_sig[t*Sn + s], 1e-3f);
}

// ---------------- gate for all 3 hypothetical states ----------------
__global__ void gate3_kernel(const float* __restrict__ gate_W1, const float* __restrict__ gate_W2,
                             const float* __restrict__ gate_b2, const float* __restrict__ se)
{
    int gw = (blockIdx.x * blockDim.x + threadIdx.x) >> 5;
    int lane = threadIdx.x & 31;
    if (gw >= Mtot * Sn) return;
    int s = gw & 3, m = gw >> 2;
    const float* W1 = gate_W1 + (size_t)s * 521 * GH;
    const float* hb = g_hgate + ((size_t)s*Mtot + m) * GH;
    float zz = g_z[m*Sn + s];
    float base0 = hb[lane]      + zz * W1[512*GH + lane];
    float base1 = hb[lane + 32] + zz * W1[512*GH + lane + 32];
    float se0[3] = {0,0,0}, se1[3] = {0,0,0};
    #pragma unroll
    for (int e = 0; e < 8; e++) {
        float wa = W1[(513+e)*GH + lane];
        float wb = W1[(513+e)*GH + lane + 32];
        #pragma unroll
        for (int st = 0; st < 3; st++) {
            float sv = se[st*8 + e];
            se0[st] += sv * wa; se1[st] += sv * wb;
        }
    }
    float w20 = gate_W2[s*GH + lane], w21 = gate_W2[s*GH + lane + 32];
    float b2 = gate_b2[s];
    #pragma unroll
    for (int st = 0; st < 3; st++) {
        float v = fmaxf(base0 + se0[st], 0.f)*w20 + fmaxf(base1 + se1[st], 0.f)*w21;
        #pragma unroll
        for (int o = 16; o; o >>= 1) v += __shfl_down_sync(0xffffffffu, v, o);
        if (!lane) g_g3[((size_t)m*Sn + s)*3 + st] = 1.f / (1.f + expf(-(v + b2)));
    }
}

__global__ void g3mean_kernel()
{
    int i = blockIdx.x * blockDim.x + threadIdx.x;
    if (i >= Tn*Sn*3) return;
    int st = i % 3, r = i / 3;
    int s = r & 3, t = r >> 2;
    float acc = 0.f;
    #pragma unroll
    for (int b = 0; b < Bb; b++)
        acc += g_g3[(((size_t)b*Tn + t)*Sn + s)*3 + st];
    g_g3m[i] = acc * 0.125f;
}

__global__ void state_scan_kernel()
{
    __shared__ float sm[12288];
    float ema = 0.5f; int cur = 0;
    for (int ph = 0; ph < 2; ph++) {
        __syncthreads();
        for (int i = threadIdx.x; i < 12288; i += blockDim.x) sm[i] = g_g3m[ph*12288 + i];
        __syncthreads();
        if (threadIdx.x < Sn) {
            int s = threadIdx.x;
            for (int tt = 0; tt < 1024; tt++) {
                int t = ph*1024 + tt;
                g_state[t*Sn + s] = cur;
                float gm = sm[(tt*Sn + s)*3 + cur];
                ema = 0.99f*ema + 0.01f*gm;
                if (cur == 0)      { if (ema < 0.1f)  cur = 1; }
                else if (cur == 1) { if (ema < 0.03f) cur = 2; else if (ema > 0.25f) cur = 0; }
                else               { if (ema > 0.25f) cur = 0; }
            }
        }
    }
}

__global__ void geff_kernel()
{
    int i = blockIdx.x * blockDim.x + threadIdx.x;
    if (i >= Mtot * Sn) return;
    int s = i & 3, m = i >> 2;
    int t = m & (Tn - 1);
    int st = g_state[t*Sn + s];
    float gn = (st == 0) ? 1.0f : ((st == 1) ? 0.5f : 0.1f);
    g_geff[i] = g_g3[(size_t)i*3 + st] * gn;
}

// ---------------- m recurrence: one thread per (b,s,d), unroll 16 ----------------
__global__ void mscan_kernel(const float* __restrict__ w0, float* __restrict__ out)
{
    int blk = blockIdx.x;              // 128 blocks x 128 threads
    int dchunk = blk & 3;
    int bs = blk >> 2;
    int s = bs & 3, b = bs >> 2;
    int d = dchunk*128 + threadIdx.x;

    const float* wp = g_wenc + ((size_t)s*Mtot + (size_t)b*Tn)*Dm + d;
    float* op = out + (size_t)b*Tn*(Sn*Dm) + s*Dm + d;
    const float* gp = g_geff + ((size_t)b*Tn)*Sn + s;

    float m = w0[s*Dm + d];
    for (int t0 = 0; t0 < Tn; t0 += 16) {
        float ge[16], w[16];
        #pragma unroll
        for (int u = 0; u < 16; u++) {
            ge[u] = __ldg(gp + (size_t)(t0+u)*Sn);
            w[u]  = __ldg(wp + (size_t)(t0+u)*Dm);
        }
        #pragma unroll
        for (int u = 0; u < 16; u++) {
            m = (1.f - ge[u])*m + ge[u]*w[u];
            op[(size_t)(t0+u)*(Sn*Dm)] = m;
        }
    }
}

// ---------------- launch ----------------
extern "C" void kernel_launch(void* const* d_in, const int* in_sizes, int n_in,
                              void* d_out, int out_size)
{
    const float* h        = (const float*)d_in[0];
    const float* pred_W   = (const float*)d_in[1];
    const float* pred_b   = (const float*)d_in[2];
    const float* gate_W1  = (const float*)d_in[3];
    const float* gate_b1  = (const float*)d_in[4];
    const float* gate_W2  = (const float*)d_in[5];
    const float* gate_b2  = (const float*)d_in[6];
    const float* write_W  = (const float*)d_in[7];
    const float* write_b  = (const float*)d_in[8];
    const float* w0       = (const float*)d_in[9];
    const float* st_embed = (const float*)d_in[10];
    float* out = (float*)d_out;

    static bool attr_done = false;
    if (!attr_done) {
        cudaFuncSetAttribute(gemm_mma, cudaFuncAttributeMaxDynamicSharedMemorySize, GEMM_SMEM);
        attr_done = true;
    }

    convA_kernel<<<(Mtot*Dm + 255)/256, 256>>>(h);
    convB_kernel<<<dim3(16, 34, Sn), dim3(32, 8)>>>(pred_W, write_W, gate_W1);

    gemm_mma<<<dim3(9, 128, Sn), 256, GEMM_SMEM>>>(pred_b, write_b, gate_b1, h);

    err_finalize_kernel<<<(Mtot*Sn + 255)/256, 256>>>();
    errmean_kernel<<<(Tn*Sn + 255)/256, 256>>>();
    scan_mu_kernel<<<1, 256>>>();
    mad_kernel<<<(Tn*Sn + 255)/256, 256>>>();
    scan_sigma_kernel<<<1, 256>>>();
    z_kernel<<<(Mtot*Sn + 255)/256, 256>>>();

    gate3_kernel<<<(Mtot*Sn*32 + 255)/256, 256>>>(gate_W1, gate_W2, gate_b2, st_embed);
    g3mean_kernel<<<(Tn*Sn*3 + 255)/256, 256>>>();
    state_scan_kernel<<<1, 256>>>();
    geff_kernel<<<(Mtot*Sn + 255)/256, 256>>>();

    mscan_kernel<<<128, 128>>>(w0, out);
}

// round 11
// speedup vs baseline: 1.4454x; 1.1376x over previous
#include <cuda_runtime.h>
#include <cuda_fp16.h>
#include <math.h>
#include <stdint.h>

#define Bb   8
#define Tn   2048
#define Dm   512
#define Sn   4
#define GH   64
#define Mtot (Bb*Tn)          // 16384
#define NROWS 1152            // 512 pred | 512 wenc | 64 gate | 64 zero-pad
#define KEXT  1024            // B row stride (lo half now unused)
#define KA    512             // A: hi only

// ---------------- scratch (static device globals; zero-initialized) ----------------
__device__ __half g_Ahf[(size_t)Mtot*KA];          // [m][k] hi only
__device__ __half g_Bhf[(size_t)Sn*NROWS*KEXT];    // [s][n][k]
__device__ float g_wenc [(size_t)Sn*Mtot*Dm];
__device__ float g_hgate[(size_t)Sn*Mtot*GH];
__device__ float g_errsq[Mtot*Sn];
__device__ float g_err [Mtot*Sn];
__device__ float g_z   [Mtot*Sn];
__device__ float g_a   [Tn*Sn];
__device__ float g_mu  [Tn*Sn];
__device__ float g_mad [Tn*Sn];
__device__ float g_sig [Tn*Sn];
__device__ float g_g3  [(size_t)Mtot*Sn*3];
__device__ float g_g3m [Tn*Sn*3];
__device__ int   g_state[Tn*Sn];
__device__ float g_geff[Mtot*Sn];

// ---------------- prep: fp32 -> fp16 hi (A); also zero errsq ----------------
__global__ void convA_kernel(const float* __restrict__ h)
{
    int i = blockIdx.x * blockDim.x + threadIdx.x;
    if (i < Mtot*Sn) g_errsq[i] = 0.f;
    if (i >= Mtot * Dm) return;
    g_Ahf[i] = __float2half(h[i]);
}

// transpose [d][n] -> [n][d] via 32x33 smem tile; hi only (no pass reads lo)
__global__ void convB_kernel(const float* __restrict__ pred_W, const float* __restrict__ write_W,
                             const float* __restrict__ gate_W1)
{
    __shared__ float tile[32][33];
    const int s = blockIdx.z;
    const int n0 = blockIdx.y * 32;      // 0..1087
    const int d0 = blockIdx.x * 32;      // 0..511
    const int tx = threadIdx.x, ty = threadIdx.y;   // 32 x 8

    const float* src; int strideN, ncol;
    if (n0 < 512)       { src = pred_W  + (size_t)s*512*512; strideN = 512; ncol = n0 + tx; }
    else if (n0 < 1024) { src = write_W + (size_t)s*512*512; strideN = 512; ncol = n0 - 512 + tx; }
    else                { src = gate_W1 + (size_t)s*521*64;  strideN = 64;  ncol = n0 - 1024 + tx; }

    #pragma unroll
    for (int i = 0; i < 4; i++)
        tile[ty + 8*i][tx] = src[(size_t)(d0 + ty + 8*i)*strideN + ncol];
    __syncthreads();
    #pragma unroll
    for (int i = 0; i < 4; i++) {
        float v = tile[tx][ty + 8*i];
        size_t base = ((size_t)s*NROWS + n0 + ty + 8*i)*KEXT + d0 + tx;
        g_Bhf[base] = __float2half(v);
    }
}

// ================= mma.sync helpers =================
__device__ __forceinline__ uint32_t smem_u32(const void* p) {
    uint32_t a;
    asm("{ .reg .u64 t; cvta.to.shared.u64 t, %1; cvt.u32.u64 %0, t; }" : "=r"(a) : "l"(p));
    return a;
}
#define CP16(dst, src) asm volatile("cp.async.cg.shared.global [%0], [%1], 16;" :: "r"(dst), "l"(src))
#define CP_COMMIT()    asm volatile("cp.async.commit_group;" ::: "memory")
#define CP_WAIT1()     asm volatile("cp.async.wait_group 1;" ::: "memory")
#define LDSM4(r0,r1,r2,r3,addr) \
    asm volatile("ldmatrix.sync.aligned.m8n8.x4.shared.b16 {%0,%1,%2,%3}, [%4];" \
        : "=r"(r0),"=r"(r1),"=r"(r2),"=r"(r3) : "r"(addr))
#define MMA16816(d, a, b) \
    asm volatile("mma.sync.aligned.m16n8k16.row.col.f32.f16.f16.f32 " \
        "{%0,%1,%2,%3},{%4,%5,%6,%7},{%8,%9},{%0,%1,%2,%3};" \
        : "+f"((d)[0]),"+f"((d)[1]),"+f"((d)[2]),"+f"((d)[3]) \
        : "r"((a)[0]),"r"((a)[1]),"r"((a)[2]),"r"((a)[3]), "r"((b)[0]),"r"((b)[1]))

#define PITCH    72
#define ROWB     (PITCH*2)          // 144 bytes per row
#define ATILE_B  (128*ROWB)         // 18432 bytes
#define BTILE_B  (128*ROWB)
#define STAGES   3
#define NT       8
#define GEMM_SMEM (STAGES*(ATILE_B + BTILE_B))   // 110592

// blockIdx.x: 0..3 preds, 4..7 wenc, 8 gate — all single-pass (K=512 hi only)
__global__ void __launch_bounds__(256, 2)
gemm_mma(const float* __restrict__ pred_b, const float* __restrict__ write_b,
         const float* __restrict__ gate_b1, const float* __restrict__ hseq)
{
    extern __shared__ __align__(16) char smem[];
    const uint32_t sAu = smem_u32(smem);
    const uint32_t sBu = sAu + STAGES*ATILE_B;

    const int tid = threadIdx.x;
    const int wid = tid >> 5, lane = tid & 31;
    const int s = blockIdx.z;
    const int mbase = blockIdx.y * 128;

    int which, nbase, colbase;
    {
        const int x = blockIdx.x;
        if (x < 4)      { which = 0; nbase = x*128;           colbase = x*128;     }
        else if (x < 8) { which = 1; nbase = 512 + (x-4)*128; colbase = (x-4)*128; }
        else            { which = 2; nbase = 1024;            colbase = 0;         }
    }

    const int mw = wid >> 2, nw = wid & 3;
    const int m0 = mw * 64;
    const int n0 = nw * 32;

    const int idx = lane & 7, sel = lane >> 3;
    const uint32_t aAddrBase = sAu + (uint32_t)(m0 + (sel&1)*8 + idx) * ROWB + (uint32_t)((sel>>1)*8)*2;
    const uint32_t bAddrBase = sBu + (uint32_t)(n0 + (sel>>1)*8 + idx) * ROWB + (uint32_t)((sel&1)*8)*2;

    float acc[4][4][4];
    #pragma unroll
    for (int i = 0; i < 4; i++)
        #pragma unroll
        for (int j = 0; j < 4; j++)
            #pragma unroll
            for (int q = 0; q < 4; q++) acc[i][j][q] = 0.f;

    const char* Aall = (const char*)g_Ahf;
    const char* Ball = (const char*)g_Bhf;

    // chunk c in [0,8): k offset c*64
    auto load_tile = [&](int c, int slot) {
        const int kcol = c * 64;
        const uint32_t ab = sAu + slot * ATILE_B;
        const uint32_t bb = sBu + slot * BTILE_B;
        #pragma unroll
        for (int it = 0; it < 4; it++) {
            int g = tid + it*256;                 // 1024 granules: row*8 + gc
            int row = g >> 3, gc = g & 7;
            CP16(ab + row*ROWB + gc*16,
                 Aall + ((size_t)(mbase + row)*KA + kcol + gc*8)*2);
        }
        #pragma unroll
        for (int it = 0; it < 4; it++) {
            int g = tid + it*256;
            int row = g >> 3, gc = g & 7;
            CP16(bb + row*ROWB + gc*16,
                 Ball + (((size_t)s*NROWS + nbase + row)*KEXT + kcol + gc*8)*2);
        }
        CP_COMMIT();
    };

    load_tile(0, 0);
    load_tile(1, 1);
    int slot = 0;
    for (int c = 0; c < NT; c++) {
        CP_WAIT1();
        __syncthreads();
        if (c + 2 < NT) load_tile(c + 2, (c + 2) % STAGES);
        else CP_COMMIT();
        const uint32_t aOff = aAddrBase + slot*ATILE_B;
        const uint32_t bOff = bAddrBase + slot*BTILE_B;
        #pragma unroll
        for (int ks = 0; ks < 4; ks++) {
            uint32_t afr[4][4], bfr[4][2];
            #pragma unroll
            for (int i = 0; i < 4; i++)
                LDSM4(afr[i][0], afr[i][1], afr[i][2], afr[i][3],
                      aOff + i*16*ROWB + ks*32);
            #pragma unroll
            for (int jp = 0; jp < 2; jp++) {
                uint32_t r0, r1, r2, r3;
                LDSM4(r0, r1, r2, r3, bOff + jp*16*ROWB + ks*32);
                bfr[jp*2+0][0] = r0; bfr[jp*2+0][1] = r1;
                bfr[jp*2+1][0] = r2; bfr[jp*2+1][1] = r3;
            }
            #pragma unroll
            for (int i = 0; i < 4; i++)
                #pragma unroll
                for (int j = 0; j < 4; j++)
                    MMA16816(acc[i][j], afr[i], bfr[j]);
        }
        slot = (slot + 1 == STAGES) ? 0 : slot + 1;
    }

    // ---------------- epilogue ----------------
    const int rbase = mbase + m0 + (lane >> 2);
    const int cbase = colbase + n0 + (lane & 3) * 2;

    if (which == 0) {
        // fused err: sum (pred - h[r+1])^2, atomic into g_errsq
        const float* bias = pred_b + s*Dm;
        float rowsum[4][2];
        #pragma unroll
        for (int i = 0; i < 4; i++) { rowsum[i][0] = 0.f; rowsum[i][1] = 0.f; }
        #pragma unroll
        for (int j = 0; j < 4; j++) {
            const int col = cbase + j*8;
            const float b0 = __ldg(bias + col), b1 = __ldg(bias + col + 1);
            #pragma unroll
            for (int i = 0; i < 4; i++) {
                const int r1 = rbase + i*16, r2 = r1 + 8;
                float2 h1 = *(const float2*)(hseq + (size_t)(r1+1)*Dm + col);
                float2 h2 = *(const float2*)(hseq + (size_t)(r2+1)*Dm + col);
                float d0 = acc[i][j][0] + b0 - h1.x;
                float d1 = acc[i][j][1] + b1 - h1.y;
                float d2 = acc[i][j][2] + b0 - h2.x;
                float d3 = acc[i][j][3] + b1 - h2.y;
                rowsum[i][0] += d0*d0 + d1*d1;
                rowsum[i][1] += d2*d2 + d3*d3;
            }
        }
        #pragma unroll
        for (int i = 0; i < 4; i++) {
            #pragma unroll
            for (int hh = 0; hh < 2; hh++) {
                float v = rowsum[i][hh];
                v += __shfl_xor_sync(0xffffffffu, v, 1);
                v += __shfl_xor_sync(0xffffffffu, v, 2);
                if ((lane & 3) == 0) {
                    int r = rbase + i*16 + hh*8;
                    if ((r & (Tn - 1)) != Tn - 1)
                        atomicAdd(&g_errsq[(r + 1)*Sn + s], v);
                }
            }
        }
        return;
    }

    if (which == 2 && n0 >= GH) return;   // gate tile: only cols 0..63 valid

    float* Cm; const float* bias; int stride;
    if (which == 1) { Cm = g_wenc + (size_t)s*Mtot*Dm; bias = write_b + s*Dm; stride = Dm; }
    else            { Cm = g_hgate + (size_t)s*Mtot*GH; bias = gate_b1 + s*GH; stride = GH; }

    #pragma unroll
    for (int j = 0; j < 4; j++) {
        const int col = cbase + j*8;
        const float b0 = __ldg(bias + col), b1 = __ldg(bias + col + 1);
        #pragma unroll
        for (int i = 0; i < 4; i++) {
            const int r = rbase + i*16;
            float2 o0 = { acc[i][j][0] + b0, acc[i][j][1] + b1 };
            float2 o1 = { acc[i][j][2] + b0, acc[i][j][3] + b1 };
            *(float2*)(Cm + (size_t)r*stride + col)       = o0;
            *(float2*)(Cm + (size_t)(r+8)*stride + col)   = o1;
        }
    }
}

// ---------------- err finalize: sqrt(sum + 1e-8), 0 at t=0 ----------------
__global__ void err_finalize_kernel()
{
    int i = blockIdx.x * blockDim.x + threadIdx.x;
    if (i >= Mtot * Sn) return;
    int t = (i >> 2) & (Tn - 1);
    g_err[i] = (t == 0) ? 0.f : sqrtf(g_errsq[i] + 1e-8f);
}

__global__ void errmean_kernel()
{
    int i = blockIdx.x * blockDim.x + threadIdx.x;
    if (i >= Tn * Sn) return;
    int s = i & 3, t = i >> 2;
    float acc = 0.f;
    #pragma unroll
    for (int b = 0; b < Bb; b++) acc += g_err[((size_t)(b*Tn + t))*Sn + s];
    g_a[i] = acc * 0.125f;
}

__global__ void scan_mu_kernel()
{
    __shared__ float sm[Tn*Sn];
    for (int i = threadIdx.x; i < Tn*Sn; i += blockDim.x) sm[i] = g_a[i];
    __syncthreads();
    if (threadIdx.x < Sn) {
        int s = threadIdx.x;
        float mu = 0.f;
        for (int t = 0; t < Tn; t++) {
            g_mu[t*Sn + s] = mu;
            if (t > 0) mu = 0.99f*mu + 0.01f*sm[t*Sn + s];
        }
    }
}

__global__ void mad_kernel()
{
    int i = blockIdx.x * blockDim.x + threadIdx.x;
    if (i >= Tn * Sn) return;
    int s = i & 3, t = i >> 2;
    float mu = g_mu[i];
    float acc = 0.f;
    #pragma unroll
    for (int b = 0; b < Bb; b++) acc += fabsf(g_err[((size_t)(b*Tn + t))*Sn + s] - mu);
    g_mad[i] = acc * 0.125f;
}

__global__ void scan_sigma_kernel()
{
    __shared__ float sm[Tn*Sn];
    for (int i = threadIdx.x; i < Tn*Sn; i += blockDim.x) sm[i] = g_mad[i];
    __syncthreads();
    if (threadIdx.x < Sn) {
        int s = threadIdx.x;
        float sg = 1.f;
        for (int t = 0; t < Tn; t++) {
            g_sig[t*Sn + s] = sg;
            if (t > 0) sg = 0.99f*sg + 0.01f*sm[t*Sn + s];
        }
    }
}

__global__ void z_kernel()
{
    int i = blockIdx.x * blockDim.x + threadIdx.x;
    if (i >= Mtot * Sn) return;
    int s = i & 3, m = i >> 2;
    int t = m & (Tn - 1);
    g_z[i] = (t == 0) ? 0.f
                      : (g_err[i] - g_mu[t*Sn + s]) / fmaxf(g_sig[t*Sn + s], 1e-3f);
}

// ---------------- gate for all 3 hypothetical states ----------------
__global__ void gate3_kernel(const float* __restrict__ gate_W1, const float* __restrict__ gate_W2,
                             const float* __restrict__ gate_b2, const float* __restrict__ se)
{
    int gw = (blockIdx.x * blockDim.x + threadIdx.x) >> 5;
    int lane = threadIdx.x & 31;
    if (gw >= Mtot * Sn) return;
    int s = gw & 3, m = gw >> 2;
    const float* W1 = gate_W1 + (size_t)s * 521 * GH;
    const float* hb = g_hgate + ((size_t)s*Mtot + m) * GH;
    float zz = g_z[m*Sn + s];
    float base0 = hb[lane]      + zz * W1[512*GH + lane];
    float base1 = hb[lane + 32] + zz * W1[512*GH + lane + 32];
    float se0[3] = {0,0,0}, se1[3] = {0,0,0};
    #pragma unroll
    for (int e = 0; e < 8; e++) {
        float wa = W1[(513+e)*GH + lane];
        float wb = W1[(513+e)*GH + lane + 32];
        #pragma unroll
        for (int st = 0; st < 3; st++) {
            float sv = se[st*8 + e];
            se0[st] += sv * wa; se1[st] += sv * wb;
        }
    }
    float w20 = gate_W2[s*GH + lane], w21 = gate_W2[s*GH + lane + 32];
    float b2 = gate_b2[s];
    #pragma unroll
    for (int st = 0; st < 3; st++) {
        float v = fmaxf(base0 + se0[st], 0.f)*w20 + fmaxf(base1 + se1[st], 0.f)*w21;
        #pragma unroll
        for (int o = 16; o; o >>= 1) v += __shfl_down_sync(0xffffffffu, v, o);
        if (!lane) g_g3[((size_t)m*Sn + s)*3 + st] = 1.f / (1.f + expf(-(v + b2)));
    }
}

__global__ void g3mean_kernel()
{
    int i = blockIdx.x * blockDim.x + threadIdx.x;
    if (i >= Tn*Sn*3) return;
    int st = i % 3, r = i / 3;
    int s = r & 3, t = r >> 2;
    float acc = 0.f;
    #pragma unroll
    for (int b = 0; b < Bb; b++)
        acc += g_g3[(((size_t)b*Tn + t)*Sn + s)*3 + st];
    g_g3m[i] = acc * 0.125f;
}

__global__ void state_scan_kernel()
{
    __shared__ float sm[12288];
    float ema = 0.5f; int cur = 0;
    for (int ph = 0; ph < 2; ph++) {
        __syncthreads();
        for (int i = threadIdx.x; i < 12288; i += blockDim.x) sm[i] = g_g3m[ph*12288 + i];
        __syncthreads();
        if (threadIdx.x < Sn) {
            int s = threadIdx.x;
            for (int tt = 0; tt < 1024; tt++) {
                int t = ph*1024 + tt;
                g_state[t*Sn + s] = cur;
                float gm = sm[(tt*Sn + s)*3 + cur];
                ema = 0.99f*ema + 0.01f*gm;
                if (cur == 0)      { if (ema < 0.1f)  cur = 1; }
                else if (cur == 1) { if (ema < 0.03f) cur = 2; else if (ema > 0.25f) cur = 0; }
                else               { if (ema > 0.25f) cur = 0; }
            }
        }
    }
}

__global__ void geff_kernel()
{
    int i = blockIdx.x * blockDim.x + threadIdx.x;
    if (i >= Mtot * Sn) return;
    int s = i & 3, m = i >> 2;
    int t = m & (Tn - 1);
    int st = g_state[t*Sn + s];
    float gn = (st == 0) ? 1.0f : ((st == 1) ? 0.5f : 0.1f);
    g_geff[i] = g_g3[(size_t)i*3 + st] * gn;
}

// ---------------- m recurrence: one thread per (b,s,d), unroll 16 ----------------
__global__ void mscan_kernel(const float* __restrict__ w0, float* __restrict__ out)
{
    int blk = blockIdx.x;              // 128 blocks x 128 threads
    int dchunk = blk & 3;
    int bs = blk >> 2;
    int s = bs & 3, b = bs >> 2;
    int d = dchunk*128 + threadIdx.x;

    const float* wp = g_wenc + ((size_t)s*Mtot + (size_t)b*Tn)*Dm + d;
    float* op = out + (size_t)b*Tn*(Sn*Dm) + s*Dm + d;
    const float* gp = g_geff + ((size_t)b*Tn)*Sn + s;

    float m = w0[s*Dm + d];
    for (int t0 = 0; t0 < Tn; t0 += 16) {
        float ge[16], w[16];
        #pragma unroll
        for (int u = 0; u < 16; u++) {
            ge[u] = __ldg(gp + (size_t)(t0+u)*Sn);
            w[u]  = __ldg(wp + (size_t)(t0+u)*Dm);
        }
        #pragma unroll
        for (int u = 0; u < 16; u++) {
            m = (1.f - ge[u])*m + ge[u]*w[u];
            op[(size_t)(t0+u)*(Sn*Dm)] = m;
        }
    }
}

// ---------------- launch ----------------
extern "C" void kernel_launch(void* const* d_in, const int* in_sizes, int n_in,
                              void* d_out, int out_size)
{
    const float* h        = (const float*)d_in[0];
    const float* pred_W   = (const float*)d_in[1];
    const float* pred_b   = (const float*)d_in[2];
    const float* gate_W1  = (const float*)d_in[3];
    const float* gate_b1  = (const float*)d_in[4];
    const float* gate_W2  = (const float*)d_in[5];
    const float* gate_b2  = (const float*)d_in[6];
    const float* write_W  = (const float*)d_in[7];
    const float* write_b  = (const float*)d_in[8];
    const float* w0       = (const float*)d_in[9];
    const float* st_embed = (const float*)d_in[10];
    float* out = (float*)d_out;

    static bool attr_done = false;
    if (!attr_done) {
        cudaFuncSetAttribute(gemm_mma, cudaFuncAttributeMaxDynamicSharedMemorySize, GEMM_SMEM);
        attr_done = true;
    }

    convA_kernel<<<(Mtot*Dm + 255)/256, 256>>>(h);
    convB_kernel<<<dim3(16, 34, Sn), dim3(32, 8)>>>(pred_W, write_W, gate_W1);

    gemm_mma<<<dim3(9, 128, Sn), 256, GEMM_SMEM>>>(pred_b, write_b, gate_b1, h);

    err_finalize_kernel<<<(Mtot*Sn + 255)/256, 256>>>();
    errmean_kernel<<<(Tn*Sn + 255)/256, 256>>>();
    scan_mu_kernel<<<1, 256>>>();
    mad_kernel<<<(Tn*Sn + 255)/256, 256>>>();
    scan_sigma_kernel<<<1, 256>>>();
    z_kernel<<<(Mtot*Sn + 255)/256, 256>>>();

    gate3_kernel<<<(Mtot*Sn*32 + 255)/256, 256>>>(gate_W1, gate_W2, gate_b2, st_embed);
    g3mean_kernel<<<(Tn*Sn*3 + 255)/256, 256>>>();
    state_scan_kernel<<<1, 256>>>();
    geff_kernel<<<(Mtot*Sn + 255)/256, 256>>>();

    mscan_kernel<<<128, 128>>>(w0, out);
}